// round 8
// baseline (speedup 1.0000x reference)
#include <cuda_runtime.h>
#include <math.h>

// ROI max pooling, bit-exact vs JAX/XLA reference (contract proven in R2):
//   coords * 0.0625f -> __float2int_rn (round-half-even)
//   bin = roi_size * RN(1/7)   (XLA folds /7 into *recip)
//   floor/ceil edges, clip [0,50], empty bin -> 0.
//
// R8 structure:
//   K1: transpose x (B,256,2500) -> g_scr (B,2500,256)  channels-last.
//   K2: grid (M, 7), block 224 = 7 warps, NO smem, NO syncthreads.
//       blockIdx.y = ph, warp = pw: one bin per warp, all 256 channels
//       (2x float4 per lane). Results stored straight to global
//       (8 scattered STG.32/lane; rows merge in L2 before writeback).

static constexpr int   kC    = 256;
static constexpr int   kH    = 50;
static constexpr int   kW    = 50;
static constexpr int   kHW   = kH * kW;        // 2500
static constexpr int   kBins = 49;
static constexpr float kScale = 0.0625f;

__device__ float g_scr[4 * kHW * kC];          // 10.24 MB channels-last scratch

// ---------------- K1: NCHW -> NHWC transpose
__global__ void __launch_bounds__(256)
transpose_kernel(const float* __restrict__ x)
{
    __shared__ float tile[32][33];
    const int b   = blockIdx.z;
    const int hw0 = blockIdx.x * 32;
    const int c0  = blockIdx.y * 32;
    const int tx  = threadIdx.x;               // 32
    const int ty  = threadIdx.y;               // 8

    const float* src = x + ((size_t)b * kC + c0) * kHW + hw0;
    #pragma unroll
    for (int k = 0; k < 4; ++k) {
        if (hw0 + tx < kHW)
            tile[ty + k * 8][tx] = src[(ty + k * 8) * kHW + tx];
    }
    __syncthreads();

    float* dst = g_scr + ((size_t)b * kHW + hw0) * kC + c0;
    #pragma unroll
    for (int k = 0; k < 4; ++k) {
        if (hw0 + ty + k * 8 < kHW)
            dst[(ty + k * 8) * kC + tx] = tile[tx][ty + k * 8];
    }
}

// ---------------- K2: one bin per warp, direct global stores
__global__ void __launch_bounds__(224)
roi_pool_nhwc(const float* __restrict__ rois,
              float* __restrict__ out)
{
    const int m    = blockIdx.x;               // ROI
    const int ph   = blockIdx.y;               // 0..6
    const int t    = threadIdx.x;
    const int lane = t & 31;
    const int pw   = t >> 5;                   // warp id = bin column 0..6

    const float* r = rois + (size_t)m * 5;

    // Uniform per-warp bin bounds (every lane computes the same values).
    const int b  = (int)r[0];
    const int x1 = __float2int_rn(r[1] * kScale);
    const int y1 = __float2int_rn(r[2] * kScale);
    const int x2 = __float2int_rn(r[3] * kScale);
    const int y2 = __float2int_rn(r[4] * kScale);

    const float roi_h = (float)max(y2 - y1 + 1, 1);
    const float roi_w = (float)max(x2 - x1 + 1, 1);
    const float kInv7 = 1.0f / 7.0f;           // RN(1/7), matches XLA
    const float bh = roi_h * kInv7;
    const float bw = roi_w * kInv7;

    const int hs = min(max((int)floorf((float)ph * bh)       + y1, 0), kH);
    const int he = min(max((int)ceilf((float)(ph + 1) * bh)  + y1, 0), kH);
    const int ws = min(max((int)floorf((float)pw * bw)       + x1, 0), kW);
    const int we = min(max((int)ceilf((float)(pw + 1) * bw)  + x1, 0), kW);

    // lane's two channel quads: c = 4*lane.. and c = 128+4*lane..
    const float4* __restrict__ base4 =
        (const float4*)g_scr + (size_t)b * (kHW * kC / 4) + lane;

    float v0 = -INFINITY, v1 = -INFINITY, v2 = -INFINITY, v3 = -INFINITY;
    float u0 = -INFINITY, u1 = -INFINITY, u2 = -INFINITY, u3 = -INFINITY;

    for (int h = hs; h < he; ++h) {
        const float4* __restrict__ p = base4 + (size_t)(h * kW + ws) * 64;
        for (int w = ws; w < we; ++w) {
            const float4 f = __ldg(p);          // channels 4*lane..+3
            const float4 g = __ldg(p + 32);     // channels 128+4*lane..+3
            v0 = fmaxf(v0, f.x); v1 = fmaxf(v1, f.y);
            v2 = fmaxf(v2, f.z); v3 = fmaxf(v3, f.w);
            u0 = fmaxf(u0, g.x); u1 = fmaxf(u1, g.y);
            u2 = fmaxf(u2, g.z); u3 = fmaxf(u3, g.w);
            p += 64;                            // next (h,w) cell
        }
    }

    const bool valid = (he > hs) && (we > ws);
    if (!valid) { v0 = v1 = v2 = v3 = u0 = u1 = u2 = u3 = 0.0f; }

    // out[m][c][ph][pw], c = 4*lane + q (+128 for u). Stride 49 floats per c.
    float* __restrict__ o =
        out + (size_t)m * (kC * kBins) + (4 * lane) * kBins + ph * 7 + pw;
    o[0 * kBins] = v0;
    o[1 * kBins] = v1;
    o[2 * kBins] = v2;
    o[3 * kBins] = v3;
    float* __restrict__ o2 = o + 128 * kBins;
    o2[0 * kBins] = u0;
    o2[1 * kBins] = u1;
    o2[2 * kBins] = u2;
    o2[3 * kBins] = u3;
}

extern "C" void kernel_launch(void* const* d_in, const int* in_sizes, int n_in,
                              void* d_out, int out_size)
{
    const float* x    = (const float*)d_in[0];
    const float* rois = (const float*)d_in[1];
    float*       out  = (float*)d_out;

    const int B = in_sizes[0] / (kC * kHW);
    const int M = in_sizes[1] / 5;

    dim3 tgrid((kHW + 31) / 32, kC / 32, B);   // (79, 8, B)
    transpose_kernel<<<tgrid, dim3(32, 8)>>>(x);

    dim3 pgrid(M, 7);                          // 1792 blocks x 7 warps
    roi_pool_nhwc<<<pgrid, 224>>>(rois, out);
}

// round 9
// speedup vs baseline: 1.4433x; 1.4433x over previous
#include <cuda_runtime.h>
#include <math.h>

// ROI max pooling, bit-exact vs JAX/XLA reference (contract proven in R2):
//   coords * 0.0625f -> __float2int_rn (round-half-even)
//   bin = roi_size * RN(1/7)   (XLA folds /7 into *recip)
//   floor/ceil edges, clip [0,50], empty bin -> 0.
//
// R9 structure:
//   K1: transpose x (B,256,2500) -> g_scr (B,2500,256)  channels-last.
//   K2: grid (M, 7, 2), block 224 = 7 warps. Block = (roi, ph, channel half).
//       Warp = pw bin, lane = channel quad (one float4/lane -> low regs,
//       ~9 blocks/SM). Gather loads coalesced & divergence-free; results
//       staged in smem and copied out in near-linear order (R8 showed
//       scattered STGs serialize in LTS).

static constexpr int   kC    = 256;
static constexpr int   kH    = 50;
static constexpr int   kW    = 50;
static constexpr int   kHW   = kH * kW;        // 2500
static constexpr int   kBins = 49;
static constexpr float kScale = 0.0625f;

__device__ float g_scr[4 * kHW * kC];          // 10.24 MB channels-last scratch

// ---------------- K1: NCHW -> NHWC transpose
__global__ void __launch_bounds__(256)
transpose_kernel(const float* __restrict__ x)
{
    __shared__ float tile[32][33];
    const int b   = blockIdx.z;
    const int hw0 = blockIdx.x * 32;
    const int c0  = blockIdx.y * 32;
    const int tx  = threadIdx.x;               // 32
    const int ty  = threadIdx.y;               // 8

    const float* src = x + ((size_t)b * kC + c0) * kHW + hw0;
    #pragma unroll
    for (int k = 0; k < 4; ++k) {
        if (hw0 + tx < kHW)
            tile[ty + k * 8][tx] = src[(ty + k * 8) * kHW + tx];
    }
    __syncthreads();

    float* dst = g_scr + ((size_t)b * kHW + hw0) * kC + c0;
    #pragma unroll
    for (int k = 0; k < 4; ++k) {
        if (hw0 + ty + k * 8 < kHW)
            dst[(ty + k * 8) * kC + tx] = tile[tx][ty + k * 8];
    }
}

// ---------------- K2: one bin per warp, 128 channels per block
__global__ void __launch_bounds__(224)
roi_pool_nhwc(const float* __restrict__ rois,
              float* __restrict__ out)
{
    __shared__ __align__(16) float sout[128 * 7];      // 3584 B

    const int m    = blockIdx.x;               // ROI
    const int ph   = blockIdx.y;               // 0..6
    const int z    = blockIdx.z;               // channel half 0..1
    const int t    = threadIdx.x;
    const int lane = t & 31;
    const int pw   = t >> 5;                   // warp id = bin column 0..6

    const float* r = rois + (size_t)m * 5;

    // Uniform per-warp bin bounds (every lane computes the same values).
    const int b  = (int)r[0];
    const int x1 = __float2int_rn(r[1] * kScale);
    const int y1 = __float2int_rn(r[2] * kScale);
    const int x2 = __float2int_rn(r[3] * kScale);
    const int y2 = __float2int_rn(r[4] * kScale);

    const float roi_h = (float)max(y2 - y1 + 1, 1);
    const float roi_w = (float)max(x2 - x1 + 1, 1);
    const float kInv7 = 1.0f / 7.0f;           // RN(1/7), matches XLA
    const float bh = roi_h * kInv7;
    const float bw = roi_w * kInv7;

    const int hs = min(max((int)floorf((float)ph * bh)       + y1, 0), kH);
    const int he = min(max((int)ceilf((float)(ph + 1) * bh)  + y1, 0), kH);
    const int ws = min(max((int)floorf((float)pw * bw)       + x1, 0), kW);
    const int we = min(max((int)ceilf((float)(pw + 1) * bw)  + x1, 0), kW);

    // lane's channel quad: c = z*128 + 4*lane .. +3
    const float4* __restrict__ base4 =
        (const float4*)g_scr + (size_t)b * (kHW * kC / 4) + z * 32 + lane;

    float v0 = -INFINITY, v1 = -INFINITY, v2 = -INFINITY, v3 = -INFINITY;

    for (int h = hs; h < he; ++h) {
        const float4* __restrict__ p = base4 + (size_t)(h * kW + ws) * 64;
        for (int w = ws; w < we; ++w) {
            const float4 f = __ldg(p);
            v0 = fmaxf(v0, f.x); v1 = fmaxf(v1, f.y);
            v2 = fmaxf(v2, f.z); v3 = fmaxf(v3, f.w);
            p += 64;                            // next (h,w) cell
        }
    }

    const bool valid = (he > hs) && (we > ws);
    float* s = sout + (4 * lane) * 7 + pw;     // local-c-major staging
    s[0 * 7] = valid ? v0 : 0.0f;
    s[1 * 7] = valid ? v1 : 0.0f;
    s[2 * 7] = valid ? v2 : 0.0f;
    s[3 * 7] = valid ? v3 : 0.0f;
    __syncthreads();

    // Block's out slice: {m, c = z*128 + cl, ph, j} -> ordered copy.
    float* __restrict__ obase =
        out + (size_t)m * (kC * kBins) + (size_t)z * (128 * kBins) + ph * 7;
    #pragma unroll
    for (int k = t; k < 128 * 7; k += 224) {    // 4 iterations
        const int cl = k / 7;
        const int j  = k - cl * 7;
        obase[cl * kBins + j] = sout[k];
    }
}

extern "C" void kernel_launch(void* const* d_in, const int* in_sizes, int n_in,
                              void* d_out, int out_size)
{
    const float* x    = (const float*)d_in[0];
    const float* rois = (const float*)d_in[1];
    float*       out  = (float*)d_out;

    const int B = in_sizes[0] / (kC * kHW);
    const int M = in_sizes[1] / 5;

    dim3 tgrid((kHW + 31) / 32, kC / 32, B);   // (79, 8, B)
    transpose_kernel<<<tgrid, dim3(32, 8)>>>(x);

    dim3 pgrid(M, 7, 2);                       // 3584 blocks x 7 warps
    roi_pool_nhwc<<<pgrid, 224>>>(rois, out);
}

// round 10
// speedup vs baseline: 1.6186x; 1.1214x over previous
#include <cuda_runtime.h>
#include <math.h>

// ROI max pooling, bit-exact vs JAX/XLA reference (contract proven in R2):
//   coords * 0.0625f -> __float2int_rn (round-half-even)
//   bin = roi_size * RN(1/7)   (XLA folds /7 into *recip)
//   floor/ceil edges, clip [0,50], empty bin -> 0.
//
// R10 structure (= R7 shape, trimmed):
//   K1: float4-vectorized NCHW->NHWC transpose into g_scr.
//   K2: grid (M, 7), block 224 = exactly 7 warps. blockIdx.y = ph,
//       warp = pw: one bin per warp, 256 channels (2x float4/lane).
//       Unroll-2 on w for doubled MLP. Smem-staged ordered epilogue
//       (R8 proved scattered global stores serialize in LTS).

static constexpr int   kC    = 256;
static constexpr int   kH    = 50;
static constexpr int   kW    = 50;
static constexpr int   kHW   = kH * kW;        // 2500 (divisible by 4)
static constexpr int   kBins = 49;
static constexpr float kScale = 0.0625f;

__device__ float g_scr[4 * kHW * kC];          // 10.24 MB channels-last scratch

// ---------------- K1: NCHW -> NHWC transpose, float4 both sides
// Tile: 32 channels x 32 hw positions. 256 threads.
__global__ void __launch_bounds__(256)
transpose_kernel(const float* __restrict__ x)
{
    __shared__ float tile[32][36];             // pad 36: LDS conflict-free,
                                               // 36*4 % 16 == 0 (STS.128 ok)
    const int b   = blockIdx.z;
    const int hw0 = blockIdx.x * 32;
    const int c0  = blockIdx.y * 32;
    const int t   = threadIdx.x;

    // Load: thread (q = t%8, c = t/8): float4 at (c0+c, hw0+4q)
    {
        const int q = t & 7;
        const int c = t >> 3;
        const int hw = hw0 + 4 * q;
        if (hw < kHW) {
            const float4 f = *(const float4*)
                (x + ((size_t)b * kC + c0 + c) * kHW + hw);
            *(float4*)&tile[c][4 * q] = f;
        }
    }
    __syncthreads();

    // Store: thread (cq = t%8, hwi = t/8): float4 of channels (c0+4cq..+3)
    // at position hw0+hwi.
    {
        const int cq  = t & 7;
        const int hwi = t >> 3;
        const int hw  = hw0 + hwi;
        if (hw < kHW) {
            float4 f;
            f.x = tile[4 * cq + 0][hwi];
            f.y = tile[4 * cq + 1][hwi];
            f.z = tile[4 * cq + 2][hwi];
            f.w = tile[4 * cq + 3][hwi];
            *(float4*)(g_scr + ((size_t)b * kHW + hw) * kC + c0 + 4 * cq) = f;
        }
    }
}

// ---------------- K2: one bin per warp, 256 channels per warp
__global__ void __launch_bounds__(224)
roi_pool_nhwc(const float* __restrict__ rois,
              float* __restrict__ out)
{
    __shared__ __align__(16) float sout[kC * 7];       // 7168 B

    const int m    = blockIdx.x;               // ROI
    const int ph   = blockIdx.y;               // 0..6
    const int t    = threadIdx.x;
    const int lane = t & 31;
    const int pw   = t >> 5;                   // warp id = bin column 0..6

    const float* r = rois + (size_t)m * 5;

    // Uniform per-warp bin bounds (every lane computes the same values).
    const int b  = (int)r[0];
    const int x1 = __float2int_rn(r[1] * kScale);
    const int y1 = __float2int_rn(r[2] * kScale);
    const int x2 = __float2int_rn(r[3] * kScale);
    const int y2 = __float2int_rn(r[4] * kScale);

    const float roi_h = (float)max(y2 - y1 + 1, 1);
    const float roi_w = (float)max(x2 - x1 + 1, 1);
    const float kInv7 = 1.0f / 7.0f;           // RN(1/7), matches XLA
    const float bh = roi_h * kInv7;
    const float bw = roi_w * kInv7;

    const int hs = min(max((int)floorf((float)ph * bh)       + y1, 0), kH);
    const int he = min(max((int)ceilf((float)(ph + 1) * bh)  + y1, 0), kH);
    const int ws = min(max((int)floorf((float)pw * bw)       + x1, 0), kW);
    const int we = min(max((int)ceilf((float)(pw + 1) * bw)  + x1, 0), kW);

    // lane's two channel quads: c = 4*lane.. and c = 128+4*lane..
    const float4* __restrict__ base4 =
        (const float4*)g_scr + (size_t)b * (kHW * kC / 4) + lane;

    float v0 = -INFINITY, v1 = -INFINITY, v2 = -INFINITY, v3 = -INFINITY;
    float u0 = -INFINITY, u1 = -INFINITY, u2 = -INFINITY, u3 = -INFINITY;

    for (int h = hs; h < he; ++h) {
        const float4* __restrict__ p = base4 + (size_t)(h * kW + ws) * 64;
        #pragma unroll 2
        for (int w = ws; w < we; ++w) {
            const float4 f = __ldg(p);          // channels 4*lane..+3
            const float4 g = __ldg(p + 32);     // channels 128+4*lane..+3
            v0 = fmaxf(v0, f.x); v1 = fmaxf(v1, f.y);
            v2 = fmaxf(v2, f.z); v3 = fmaxf(v3, f.w);
            u0 = fmaxf(u0, g.x); u1 = fmaxf(u1, g.y);
            u2 = fmaxf(u2, g.z); u3 = fmaxf(u3, g.w);
            p += 64;                            // next (h,w) cell
        }
    }

    const bool valid = (he > hs) && (we > ws);
    float* s = sout + (4 * lane) * 7 + pw;      // c-major staging
    s[0 * 7] = valid ? v0 : 0.0f;
    s[1 * 7] = valid ? v1 : 0.0f;
    s[2 * 7] = valid ? v2 : 0.0f;
    s[3 * 7] = valid ? v3 : 0.0f;
    float* s2 = s + 128 * 7;
    s2[0 * 7] = valid ? u0 : 0.0f;
    s2[1 * 7] = valid ? u1 : 0.0f;
    s2[2 * 7] = valid ? u2 : 0.0f;
    s2[3 * 7] = valid ? u3 : 0.0f;
    __syncthreads();

    // Block's out slice: {m, c, ph, j} for all c, j -> ordered copy.
    float* __restrict__ obase = out + (size_t)m * (kC * kBins) + ph * 7;
    #pragma unroll
    for (int k = t; k < kC * 7; k += 224) {     // 8 iterations
        const int c = k / 7;
        const int j = k - c * 7;
        obase[c * kBins + j] = sout[k];
    }
}

extern "C" void kernel_launch(void* const* d_in, const int* in_sizes, int n_in,
                              void* d_out, int out_size)
{
    const float* x    = (const float*)d_in[0];
    const float* rois = (const float*)d_in[1];
    float*       out  = (float*)d_out;

    const int B = in_sizes[0] / (kC * kHW);
    const int M = in_sizes[1] / 5;

    dim3 tgrid((kHW + 31) / 32, kC / 32, B);   // (79, 8, B)
    transpose_kernel<<<tgrid, 256>>>(x);

    dim3 pgrid(M, 7);                          // 1792 blocks x 7 warps
    roi_pool_nhwc<<<pgrid, 224>>>(rois, out);
}